// round 3
// baseline (speedup 1.0000x reference)
#include <cuda_runtime.h>
#include <math.h>

#define B_ 4
#define T_ 1024
#define C_ 1024
#define H_ 16
#define D_ 64
#define HD_ (H_*D_)

// Scratch (allocation-free rule: __device__ globals)
__device__ float g_q[(size_t)B_*H_*T_*D_];
__device__ float g_k[(size_t)B_*H_*T_*D_];
__device__ float g_v[(size_t)B_*H_*T_*D_];
__device__ float g_att[(size_t)B_*T_*HD_];   // [B, T, H, D] = [B, T, HD]

// ---------------------------------------------------------------------------
// Shared 64x64 tiled SGEMM body: C[64 rows x 64 cols] starting at (m0, n0).
// 256 threads, each computes a 4x4 micro-tile. K tiled by 16.
// A: [M x K] row-major (lda), B: [K x N] row-major (ldb), C row-major (ldc).
// ---------------------------------------------------------------------------
__device__ __forceinline__ void gemm64x64(const float* __restrict__ A, int lda,
                                          const float* __restrict__ Bm, int ldb,
                                          const float* __restrict__ bias,
                                          float* __restrict__ Cm, int ldc,
                                          int Kdim, int m0, int n0)
{
    __shared__ float As[16][64];   // As[k][m] (A transposed into smem)
    __shared__ float Bs[16][68];   // Bs[k][n] (padded)

    const int tid = threadIdx.x;
    const int tx = tid & 15;       // micro col group
    const int ty = tid >> 4;       // micro row group
    const int lr = tid >> 2;       // A-load row 0..63
    const int lc = (tid & 3) * 4;  // A-load col group within 16
    const int br = tid >> 4;       // B-load row 0..15
    const int bc = (tid & 15) * 4; // B-load col

    float acc[4][4];
    #pragma unroll
    for (int i = 0; i < 4; i++)
        #pragma unroll
        for (int j = 0; j < 4; j++) acc[i][j] = 0.0f;

    for (int kt = 0; kt < Kdim; kt += 16) {
        float4 av = *(const float4*)(A + (size_t)(m0 + lr) * lda + kt + lc);
        As[lc + 0][lr] = av.x;
        As[lc + 1][lr] = av.y;
        As[lc + 2][lr] = av.z;
        As[lc + 3][lr] = av.w;
        float4 bv = *(const float4*)(Bm + (size_t)(kt + br) * ldb + n0 + bc);
        *(float4*)&Bs[br][bc] = bv;
        __syncthreads();

        #pragma unroll
        for (int k = 0; k < 16; ++k) {
            float4 a4 = *(const float4*)&As[k][ty * 4];
            float4 b4 = *(const float4*)&Bs[k][tx * 4];
            float ar[4] = {a4.x, a4.y, a4.z, a4.w};
            float br4[4] = {b4.x, b4.y, b4.z, b4.w};
            #pragma unroll
            for (int i = 0; i < 4; i++)
                #pragma unroll
                for (int j = 0; j < 4; j++)
                    acc[i][j] += ar[i] * br4[j];
        }
        __syncthreads();
    }

    float4 bb = make_float4(0.f, 0.f, 0.f, 0.f);
    if (bias) bb = *(const float4*)(bias + n0 + tx * 4);

    #pragma unroll
    for (int i = 0; i < 4; i++) {
        float4 o;
        o.x = acc[i][0] + bb.x;
        o.y = acc[i][1] + bb.y;
        o.z = acc[i][2] + bb.z;
        o.w = acc[i][3] + bb.w;
        *(float4*)(Cm + (size_t)(m0 + ty * 4 + i) * ldc + n0 + tx * 4) = o;
    }
}

// ---------------------------------------------------------------------------
// Kernel 1: QKV projections. q/k/v[b,h,t,d] = sum_c x[b,t,c] * W[h,c,d]
// grid = (T/64, B*H, 3), block = 256
// ---------------------------------------------------------------------------
__global__ void qkv_kernel(const float* __restrict__ x,
                           const float* __restrict__ Wq,
                           const float* __restrict__ Wk,
                           const float* __restrict__ Wv)
{
    const int bh = blockIdx.y;
    const int b = bh >> 4;
    const int h = bh & 15;
    const int which = blockIdx.z;
    const float* W = (which == 0 ? Wq : (which == 1 ? Wk : Wv)) + (size_t)h * C_ * D_;
    float* dst = (which == 0 ? g_q : (which == 1 ? g_k : g_v)) + (size_t)bh * T_ * D_;
    gemm64x64(x + (size_t)b * T_ * C_, C_, W, D_, nullptr, dst, D_, C_,
              blockIdx.x * 64, 0);
}

// ---------------------------------------------------------------------------
// Kernel 2: causal flash attention, fp32, online softmax.
// grid = (T/64, B*H), block = 256, dynamic smem = 4*64*68*4 bytes
// Each block: 64 queries of one (b,h). Streams 64-key tiles.
// Thread (tx,ty) owns 4 rows x 4 cols micro-tiles of S and O.
// ---------------------------------------------------------------------------
__global__ void attn_kernel()
{
    extern __shared__ float sm[];
    const int S = 68;
    float* Qst = sm;               // [64][S]  Qst[d][r]  (d-major, pre-scaled)
    float* Kst = Qst + 64 * S;     // [64][S]  Kst[d][c]
    float* Vs  = Kst + 64 * S;     // [64][S]  Vs[s][c]   (natural)
    float* Pst = Vs  + 64 * S;     // [64][S]  Pst[s][r]  (s-major)

    const int qt = blockIdx.x;
    const int bh = blockIdx.y;
    const int b = bh >> 4;
    const int h = bh & 15;
    const float* qg = g_q + (size_t)bh * T_ * D_;
    const float* kg = g_k + (size_t)bh * T_ * D_;
    const float* vg = g_v + (size_t)bh * T_ * D_;

    const int tid = threadIdx.x;
    const int tx = tid & 15;
    const int ty = tid >> 4;
    const int lr = tid >> 2;       // load row 0..63
    const int lc = (tid & 3) * 4;  // load col sub-offset 0..12

    // Load full Q tile 64x64 (transposed, pre-scaled by 1/sqrt(D)).
    // 256 threads x 4 float4 = 4096 floats.
    #pragma unroll
    for (int cc = 0; cc < 64; cc += 16) {
        const int c = cc + lc;
        float4 qv = *(const float4*)(qg + (size_t)(qt * 64 + lr) * D_ + c);
        Qst[(c + 0) * S + lr] = qv.x * 0.125f;
        Qst[(c + 1) * S + lr] = qv.y * 0.125f;
        Qst[(c + 2) * S + lr] = qv.z * 0.125f;
        Qst[(c + 3) * S + lr] = qv.w * 0.125f;
    }

    float m_i[4], l_i[4], acc[4][4];
    #pragma unroll
    for (int i = 0; i < 4; i++) {
        m_i[i] = -1e30f;
        l_i[i] = 0.0f;
        #pragma unroll
        for (int j = 0; j < 4; j++) acc[i][j] = 0.0f;
    }

    for (int kt = 0; kt <= qt; ++kt) {
        __syncthreads();  // previous-iter Vs/Pst readers done before overwrite
        #pragma unroll
        for (int cc = 0; cc < 64; cc += 16) {
            const int c = cc + lc;
            float4 kv = *(const float4*)(kg + (size_t)(kt * 64 + lr) * D_ + c);
            Kst[(c + 0) * S + lr] = kv.x;
            Kst[(c + 1) * S + lr] = kv.y;
            Kst[(c + 2) * S + lr] = kv.z;
            Kst[(c + 3) * S + lr] = kv.w;
            float4 vv = *(const float4*)(vg + (size_t)(kt * 64 + lr) * D_ + c);
            *(float4*)&Vs[lr * S + c] = vv;
        }
        __syncthreads();

        // S = Q @ K^T (this tile): 4x4 micro
        float s4[4][4];
        #pragma unroll
        for (int i = 0; i < 4; i++)
            #pragma unroll
            for (int j = 0; j < 4; j++) s4[i][j] = 0.0f;

        #pragma unroll 16
        for (int d = 0; d < 64; ++d) {
            float4 a4 = *(const float4*)&Qst[d * S + ty * 4];
            float4 b4 = *(const float4*)&Kst[d * S + tx * 4];
            float ar[4] = {a4.x, a4.y, a4.z, a4.w};
            float br4[4] = {b4.x, b4.y, b4.z, b4.w};
            #pragma unroll
            for (int i = 0; i < 4; i++)
                #pragma unroll
                for (int j = 0; j < 4; j++)
                    s4[i][j] += ar[i] * br4[j];
        }

        // causal mask on the diagonal tile
        if (kt == qt) {
            #pragma unroll
            for (int i = 0; i < 4; i++)
                #pragma unroll
                for (int j = 0; j < 4; j++)
                    if (tx * 4 + j > ty * 4 + i) s4[i][j] = -1e30f;
        }

        // online softmax per row (row reduction across the 16 tx lanes)
        #pragma unroll
        for (int i = 0; i < 4; i++) {
            float mt = fmaxf(fmaxf(s4[i][0], s4[i][1]), fmaxf(s4[i][2], s4[i][3]));
            mt = fmaxf(mt, __shfl_xor_sync(0xffffffffu, mt, 1));
            mt = fmaxf(mt, __shfl_xor_sync(0xffffffffu, mt, 2));
            mt = fmaxf(mt, __shfl_xor_sync(0xffffffffu, mt, 4));
            mt = fmaxf(mt, __shfl_xor_sync(0xffffffffu, mt, 8));
            float m_new = fmaxf(m_i[i], mt);
            float alpha = __expf(m_i[i] - m_new);
            float ls = 0.0f;
            #pragma unroll
            for (int j = 0; j < 4; j++) {
                float p = __expf(s4[i][j] - m_new);
                Pst[(tx * 4 + j) * S + ty * 4 + i] = p;
                ls += p;
            }
            ls += __shfl_xor_sync(0xffffffffu, ls, 1);
            ls += __shfl_xor_sync(0xffffffffu, ls, 2);
            ls += __shfl_xor_sync(0xffffffffu, ls, 4);
            ls += __shfl_xor_sync(0xffffffffu, ls, 8);
            l_i[i] = l_i[i] * alpha + ls;
            m_i[i] = m_new;
            #pragma unroll
            for (int j = 0; j < 4; j++) acc[i][j] *= alpha;
        }
        __syncthreads();  // Pst fully written

        // O += P @ V : 4x4 micro over s
        #pragma unroll 16
        for (int s = 0; s < 64; ++s) {
            float4 p4 = *(const float4*)&Pst[s * S + ty * 4];
            float4 v4 = *(const float4*)&Vs[s * S + tx * 4];
            float pr[4] = {p4.x, p4.y, p4.z, p4.w};
            float vr[4] = {v4.x, v4.y, v4.z, v4.w};
            #pragma unroll
            for (int i = 0; i < 4; i++)
                #pragma unroll
                for (int j = 0; j < 4; j++)
                    acc[i][j] += pr[i] * vr[j];
        }
    }

    // epilogue: normalize and write to [B, T, H, D]
    #pragma unroll
    for (int i = 0; i < 4; i++) {
        float inv = 1.0f / l_i[i];
        int t = qt * 64 + ty * 4 + i;
        float4 o;
        o.x = acc[i][0] * inv;
        o.y = acc[i][1] * inv;
        o.z = acc[i][2] * inv;
        o.w = acc[i][3] * inv;
        *(float4*)(g_att + ((size_t)(b * T_ + t) * H_ + h) * D_ + tx * 4) = o;
    }
}

// ---------------------------------------------------------------------------
// Kernel 3: output projection. out[m,n] = att[m,:] @ Wp[:,n] + bp[n]
// grid = (C/64, B*T/64), block = 256
// ---------------------------------------------------------------------------
__global__ void proj_kernel(const float* __restrict__ Wp,
                            const float* __restrict__ bp,
                            float* __restrict__ out)
{
    gemm64x64(g_att, HD_, Wp, C_, bp, out, C_, HD_,
              blockIdx.y * 64, blockIdx.x * 64);
}

// ---------------------------------------------------------------------------
extern "C" void kernel_launch(void* const* d_in, const int* in_sizes, int n_in,
                              void* d_out, int out_size)
{
    const float* x  = (const float*)d_in[0];
    const float* Wq = (const float*)d_in[1];
    const float* Wk = (const float*)d_in[2];
    const float* Wv = (const float*)d_in[3];
    const float* Wp = (const float*)d_in[4];
    const float* bp = (const float*)d_in[5];
    float* out = (float*)d_out;

    (void)in_sizes; (void)n_in; (void)out_size;

    // QKV projections
    {
        dim3 grid(T_ / 64, B_ * H_, 3);
        qkv_kernel<<<grid, 256>>>(x, Wq, Wk, Wv);
    }

    // Attention (68 KB dynamic smem)
    {
        const int smem = 4 * 64 * 68 * sizeof(float);
        cudaFuncSetAttribute(attn_kernel,
                             cudaFuncAttributeMaxDynamicSharedMemorySize, smem);
        dim3 grid(T_ / 64, B_ * H_);
        attn_kernel<<<grid, 256, smem>>>();
    }

    // Output projection
    {
        dim3 grid(C_ / 64, (B_ * T_) / 64);
        proj_kernel<<<grid, 256>>>(Wp, bp, out);
    }
}

// round 4
// speedup vs baseline: 1.9621x; 1.9621x over previous
#include <cuda_runtime.h>
#include <math.h>

#define B_ 4
#define T_ 1024
#define C_ 1024
#define H_ 16
#define D_ 64
#define HD_ (H_*D_)

// Scratch (allocation-free rule: __device__ globals)
__device__ float g_q[(size_t)B_*H_*T_*D_];
__device__ float g_k[(size_t)B_*H_*T_*D_];
__device__ float g_v[(size_t)B_*H_*T_*D_];
__device__ float g_att[(size_t)B_*T_*HD_];   // [B, T, H, D] = [B, T, HD]

// ---------------------------------------------------------------------------
// fp32 -> tf32 (round to nearest) as raw bits
// ---------------------------------------------------------------------------
__device__ __forceinline__ float f2tf32(float f) {
    unsigned u;
    asm("cvt.rna.tf32.f32 %0, %1;" : "=r"(u) : "f"(f));
    return __uint_as_float(u);
}

__device__ __forceinline__ void mma_tf32(float c[4], const unsigned a[4],
                                         const unsigned b[2]) {
    asm("mma.sync.aligned.m16n8k8.row.col.f32.tf32.tf32.f32 "
        "{%0,%1,%2,%3}, {%4,%5,%6,%7}, {%8,%9}, {%0,%1,%2,%3};"
        : "+f"(c[0]), "+f"(c[1]), "+f"(c[2]), "+f"(c[3])
        : "r"(a[0]), "r"(a[1]), "r"(a[2]), "r"(a[3]), "r"(b[0]), "r"(b[1]));
}

// ---------------------------------------------------------------------------
// TF32 tensor-core GEMM tile: C[m0:m0+128, n0:n0+64] = A @ B (+bias)
// A row-major [M,K] (lda), B row-major [K,N] (ldb), C row-major (ldc).
// 256 threads = 8 warps (4 m-warps x 2 n-warps), warp tile 32x32,
// per warp 2 m16-tiles x 4 n8-tiles, BK=32 (4 k-steps of 8).
// ---------------------------------------------------------------------------
__device__ __forceinline__ void gemm128x64_tf32(
    const float* __restrict__ A, int lda,
    const float* __restrict__ Bm, int ldb,
    const float* __restrict__ bias,
    float* __restrict__ Cm, int ldc,
    int Kdim, int m0, int n0)
{
    __shared__ float As[128][36];   // pad 36: conflict-free frag reads, 16B-aligned stores
    __shared__ float Bs[32][72];    // pad 72: conflict-free frag reads

    const int tid  = threadIdx.x;
    const int warp = tid >> 5;
    const int lane = tid & 31;
    const int wm0  = (warp >> 1) * 32;   // warp m offset within block tile
    const int wn0  = (warp & 1) * 32;    // warp n offset
    const int gid  = lane >> 2;          // group id 0..7
    const int tig  = lane & 3;           // thread-in-group 0..3

    // Global load mapping (float4 granularity)
    const int a_row = tid >> 3;          // + 32*i, i<4  -> rows 0..127
    const int a_cg  = (tid & 7) * 4;     // col within BK tile
    const int b_row = tid >> 4;          // + 16*i, i<2  -> rows 0..31
    const int b_cg  = (tid & 15) * 4;    // col within BN tile

    float4 areg[4], breg[2];

    // prefetch tile kt=0
    #pragma unroll
    for (int i = 0; i < 4; i++)
        areg[i] = *(const float4*)(A + (size_t)(m0 + a_row + 32 * i) * lda + a_cg);
    #pragma unroll
    for (int i = 0; i < 2; i++)
        breg[i] = *(const float4*)(Bm + (size_t)(b_row + 16 * i) * ldb + n0 + b_cg);

    float acc[2][4][4];
    #pragma unroll
    for (int i = 0; i < 2; i++)
        #pragma unroll
        for (int j = 0; j < 4; j++)
            #pragma unroll
            for (int r = 0; r < 4; r++) acc[i][j][r] = 0.0f;

    for (int kt = 0; kt < Kdim; kt += 32) {
        // store prefetched tile to smem (tf32-rounded)
        #pragma unroll
        for (int i = 0; i < 4; i++) {
            float* p = &As[a_row + 32 * i][a_cg];
            p[0] = f2tf32(areg[i].x);
            p[1] = f2tf32(areg[i].y);
            p[2] = f2tf32(areg[i].z);
            p[3] = f2tf32(areg[i].w);
        }
        #pragma unroll
        for (int i = 0; i < 2; i++) {
            float* p = &Bs[b_row + 16 * i][b_cg];
            p[0] = f2tf32(breg[i].x);
            p[1] = f2tf32(breg[i].y);
            p[2] = f2tf32(breg[i].z);
            p[3] = f2tf32(breg[i].w);
        }
        __syncthreads();

        // prefetch next tile
        if (kt + 32 < Kdim) {
            #pragma unroll
            for (int i = 0; i < 4; i++)
                areg[i] = *(const float4*)(A + (size_t)(m0 + a_row + 32 * i) * lda + kt + 32 + a_cg);
            #pragma unroll
            for (int i = 0; i < 2; i++)
                breg[i] = *(const float4*)(Bm + (size_t)(kt + 32 + b_row + 16 * i) * ldb + n0 + b_cg);
        }

        // compute BK=32 (4 k-steps)
        #pragma unroll
        for (int ks = 0; ks < 4; ks++) {
            const int k0 = ks * 8;
            unsigned a[2][4], b[4][2];
            #pragma unroll
            for (int i = 0; i < 2; i++) {
                const int r = wm0 + i * 16 + gid;
                a[i][0] = __float_as_uint(As[r    ][k0 + tig    ]);
                a[i][1] = __float_as_uint(As[r + 8][k0 + tig    ]);
                a[i][2] = __float_as_uint(As[r    ][k0 + tig + 4]);
                a[i][3] = __float_as_uint(As[r + 8][k0 + tig + 4]);
            }
            #pragma unroll
            for (int j = 0; j < 4; j++) {
                const int n = wn0 + j * 8 + gid;
                b[j][0] = __float_as_uint(Bs[k0 + tig    ][n]);
                b[j][1] = __float_as_uint(Bs[k0 + tig + 4][n]);
            }
            #pragma unroll
            for (int i = 0; i < 2; i++)
                #pragma unroll
                for (int j = 0; j < 4; j++)
                    mma_tf32(acc[i][j], a[i], b[j]);
        }
        __syncthreads();
    }

    // epilogue: c0,c1 at (row, 2*tig), (row, 2*tig+1); c2,c3 at row+8
    #pragma unroll
    for (int i = 0; i < 2; i++) {
        const int r = m0 + wm0 + i * 16 + gid;
        #pragma unroll
        for (int j = 0; j < 4; j++) {
            const int c = n0 + wn0 + j * 8 + 2 * tig;
            float bx = 0.f, by = 0.f;
            if (bias) { bx = bias[c]; by = bias[c + 1]; }
            float2 o0 = make_float2(acc[i][j][0] + bx, acc[i][j][1] + by);
            float2 o1 = make_float2(acc[i][j][2] + bx, acc[i][j][3] + by);
            *(float2*)(Cm + (size_t)r * ldc + c) = o0;
            *(float2*)(Cm + (size_t)(r + 8) * ldc + c) = o1;
        }
    }
}

// ---------------------------------------------------------------------------
// Kernel 1: QKV projections (tensor cores).
// grid = (T/128, B*H, 3), block = 256
// ---------------------------------------------------------------------------
__global__ __launch_bounds__(256) void qkv_kernel(const float* __restrict__ x,
                                                  const float* __restrict__ Wq,
                                                  const float* __restrict__ Wk,
                                                  const float* __restrict__ Wv)
{
    const int bh = blockIdx.y;
    const int b = bh >> 4;
    const int h = bh & 15;
    const int which = blockIdx.z;
    const float* W = (which == 0 ? Wq : (which == 1 ? Wk : Wv)) + (size_t)h * C_ * D_;
    float* dst = (which == 0 ? g_q : (which == 1 ? g_k : g_v)) + (size_t)bh * T_ * D_;
    gemm128x64_tf32(x + (size_t)b * T_ * C_, C_, W, D_, nullptr, dst, D_, C_,
                    blockIdx.x * 128, 0);
}

// ---------------------------------------------------------------------------
// Kernel 2: causal flash attention, fp32, online softmax. (unchanged, passing)
// grid = (T/64, B*H), block = 256, dynamic smem = 4*64*68*4 bytes
// ---------------------------------------------------------------------------
__global__ void attn_kernel()
{
    extern __shared__ float sm[];
    const int S = 68;
    float* Qst = sm;               // [64][S]  Qst[d][r]  (d-major, pre-scaled)
    float* Kst = Qst + 64 * S;     // [64][S]  Kst[d][c]
    float* Vs  = Kst + 64 * S;     // [64][S]  Vs[s][c]   (natural)
    float* Pst = Vs  + 64 * S;     // [64][S]  Pst[s][r]  (s-major)

    const int qt = blockIdx.x;
    const int bh = blockIdx.y;
    const int b = bh >> 4;
    const int h = bh & 15;
    const float* qg = g_q + (size_t)bh * T_ * D_;
    const float* kg = g_k + (size_t)bh * T_ * D_;
    const float* vg = g_v + (size_t)bh * T_ * D_;

    const int tid = threadIdx.x;
    const int tx = tid & 15;
    const int ty = tid >> 4;
    const int lr = tid >> 2;       // load row 0..63
    const int lc = (tid & 3) * 4;  // load col sub-offset 0..12

    #pragma unroll
    for (int cc = 0; cc < 64; cc += 16) {
        const int c = cc + lc;
        float4 qv = *(const float4*)(qg + (size_t)(qt * 64 + lr) * D_ + c);
        Qst[(c + 0) * S + lr] = qv.x * 0.125f;
        Qst[(c + 1) * S + lr] = qv.y * 0.125f;
        Qst[(c + 2) * S + lr] = qv.z * 0.125f;
        Qst[(c + 3) * S + lr] = qv.w * 0.125f;
    }

    float m_i[4], l_i[4], acc[4][4];
    #pragma unroll
    for (int i = 0; i < 4; i++) {
        m_i[i] = -1e30f;
        l_i[i] = 0.0f;
        #pragma unroll
        for (int j = 0; j < 4; j++) acc[i][j] = 0.0f;
    }

    for (int kt = 0; kt <= qt; ++kt) {
        __syncthreads();  // previous-iter Vs/Pst readers done before overwrite
        #pragma unroll
        for (int cc = 0; cc < 64; cc += 16) {
            const int c = cc + lc;
            float4 kv = *(const float4*)(kg + (size_t)(kt * 64 + lr) * D_ + c);
            Kst[(c + 0) * S + lr] = kv.x;
            Kst[(c + 1) * S + lr] = kv.y;
            Kst[(c + 2) * S + lr] = kv.z;
            Kst[(c + 3) * S + lr] = kv.w;
            float4 vv = *(const float4*)(vg + (size_t)(kt * 64 + lr) * D_ + c);
            *(float4*)&Vs[lr * S + c] = vv;
        }
        __syncthreads();

        // S = Q @ K^T (this tile): 4x4 micro
        float s4[4][4];
        #pragma unroll
        for (int i = 0; i < 4; i++)
            #pragma unroll
            for (int j = 0; j < 4; j++) s4[i][j] = 0.0f;

        #pragma unroll 16
        for (int d = 0; d < 64; ++d) {
            float4 a4 = *(const float4*)&Qst[d * S + ty * 4];
            float4 b4 = *(const float4*)&Kst[d * S + tx * 4];
            float ar[4] = {a4.x, a4.y, a4.z, a4.w};
            float br4[4] = {b4.x, b4.y, b4.z, b4.w};
            #pragma unroll
            for (int i = 0; i < 4; i++)
                #pragma unroll
                for (int j = 0; j < 4; j++)
                    s4[i][j] += ar[i] * br4[j];
        }

        if (kt == qt) {
            #pragma unroll
            for (int i = 0; i < 4; i++)
                #pragma unroll
                for (int j = 0; j < 4; j++)
                    if (tx * 4 + j > ty * 4 + i) s4[i][j] = -1e30f;
        }

        #pragma unroll
        for (int i = 0; i < 4; i++) {
            float mt = fmaxf(fmaxf(s4[i][0], s4[i][1]), fmaxf(s4[i][2], s4[i][3]));
            mt = fmaxf(mt, __shfl_xor_sync(0xffffffffu, mt, 1));
            mt = fmaxf(mt, __shfl_xor_sync(0xffffffffu, mt, 2));
            mt = fmaxf(mt, __shfl_xor_sync(0xffffffffu, mt, 4));
            mt = fmaxf(mt, __shfl_xor_sync(0xffffffffu, mt, 8));
            float m_new = fmaxf(m_i[i], mt);
            float alpha = __expf(m_i[i] - m_new);
            float ls = 0.0f;
            #pragma unroll
            for (int j = 0; j < 4; j++) {
                float p = __expf(s4[i][j] - m_new);
                Pst[(tx * 4 + j) * S + ty * 4 + i] = p;
                ls += p;
            }
            ls += __shfl_xor_sync(0xffffffffu, ls, 1);
            ls += __shfl_xor_sync(0xffffffffu, ls, 2);
            ls += __shfl_xor_sync(0xffffffffu, ls, 4);
            ls += __shfl_xor_sync(0xffffffffu, ls, 8);
            l_i[i] = l_i[i] * alpha + ls;
            m_i[i] = m_new;
            #pragma unroll
            for (int j = 0; j < 4; j++) acc[i][j] *= alpha;
        }
        __syncthreads();  // Pst fully written

        #pragma unroll 16
        for (int s = 0; s < 64; ++s) {
            float4 p4 = *(const float4*)&Pst[s * S + ty * 4];
            float4 v4 = *(const float4*)&Vs[s * S + tx * 4];
            float pr[4] = {p4.x, p4.y, p4.z, p4.w};
            float vr[4] = {v4.x, v4.y, v4.z, v4.w};
            #pragma unroll
            for (int i = 0; i < 4; i++)
                #pragma unroll
                for (int j = 0; j < 4; j++)
                    acc[i][j] += pr[i] * vr[j];
        }
    }

    #pragma unroll
    for (int i = 0; i < 4; i++) {
        float inv = 1.0f / l_i[i];
        int t = qt * 64 + ty * 4 + i;
        float4 o;
        o.x = acc[i][0] * inv;
        o.y = acc[i][1] * inv;
        o.z = acc[i][2] * inv;
        o.w = acc[i][3] * inv;
        *(float4*)(g_att + ((size_t)(b * T_ + t) * H_ + h) * D_ + tx * 4) = o;
    }
}

// ---------------------------------------------------------------------------
// Kernel 3: output projection (tensor cores). out = att @ Wp + bp
// grid = (C/64, B*T/128), block = 256
// ---------------------------------------------------------------------------
__global__ __launch_bounds__(256) void proj_kernel(const float* __restrict__ Wp,
                                                   const float* __restrict__ bp,
                                                   float* __restrict__ out)
{
    gemm128x64_tf32(g_att, HD_, Wp, C_, bp, out, C_, HD_,
                    blockIdx.y * 128, blockIdx.x * 64);
}

// ---------------------------------------------------------------------------
extern "C" void kernel_launch(void* const* d_in, const int* in_sizes, int n_in,
                              void* d_out, int out_size)
{
    const float* x  = (const float*)d_in[0];
    const float* Wq = (const float*)d_in[1];
    const float* Wk = (const float*)d_in[2];
    const float* Wv = (const float*)d_in[3];
    const float* Wp = (const float*)d_in[4];
    const float* bp = (const float*)d_in[5];
    float* out = (float*)d_out;

    (void)in_sizes; (void)n_in; (void)out_size;

    // QKV projections (tensor cores)
    {
        dim3 grid(T_ / 128, B_ * H_, 3);
        qkv_kernel<<<grid, 256>>>(x, Wq, Wk, Wv);
    }

    // Attention (68 KB dynamic smem)
    {
        const int smem = 4 * 64 * 68 * sizeof(float);
        cudaFuncSetAttribute(attn_kernel,
                             cudaFuncAttributeMaxDynamicSharedMemorySize, smem);
        dim3 grid(T_ / 64, B_ * H_);
        attn_kernel<<<grid, 256, smem>>>();
    }

    // Output projection (tensor cores)
    {
        dim3 grid(C_ / 64, (B_ * T_) / 128);
        proj_kernel<<<grid, 256>>>(Wp, bp, out);
    }
}